// round 1
// baseline (speedup 1.0000x reference)
#include <cuda_runtime.h>
#include <math.h>

// ---------------------------------------------------------------------------
// TriangleAttention  (B=1, N=256, IN_DIM=128, H=4, D=32)
// Pipeline: LN -> GEMM(qkv) -> pair-bias -> GEMM(gate,sigmoid)
//           -> attention per (row r, head h) -> GEMM(out, gate*ao fused)
// All fp32 SIMT this round (baseline).
// ---------------------------------------------------------------------------

#define NPOS 65536          // 256*256 positions
#define NSEQ 256
#define INDIM 128
#define NH 4
#define HD 32

// Scratch (static device memory: allowed; no allocation APIs used)
__device__ float g_zn[NPOS * INDIM];     // layernormed z
__device__ float g_q[NPOS * INDIM];      // layout [r][h][i][d]
__device__ float g_k[NPOS * INDIM];      // layout [r][h][j][d]
__device__ float g_v[NPOS * INDIM];      // layout [r][h][j][d]
__device__ float g_pb[NH * NPOS];        // layout [h][i][j]
__device__ float g_gate[NPOS * INDIM];   // sigmoid gate, [p][c]
__device__ float g_ao[NPOS * INDIM];     // attention out, [p][h*32+d]

__device__ __forceinline__ float warp_sum(float v) {
    #pragma unroll
    for (int o = 16; o; o >>= 1) v += __shfl_xor_sync(0xffffffffu, v, o);
    return v;
}
__device__ __forceinline__ float warp_max(float v) {
    #pragma unroll
    for (int o = 16; o; o >>= 1) v = fmaxf(v, __shfl_xor_sync(0xffffffffu, v, o));
    return v;
}

// ---------------------------------------------------------------------------
// LayerNorm: one warp per 128-elem row. 8 rows / block.
// ---------------------------------------------------------------------------
__global__ void __launch_bounds__(256) ln_kernel(
    const float* __restrict__ z, const float* __restrict__ g,
    const float* __restrict__ b)
{
    int w = threadIdx.x >> 5, lane = threadIdx.x & 31;
    int row = blockIdx.x * 8 + w;
    float4 zv = *(const float4*)&z[row * INDIM + (lane << 2)];
    float s  = zv.x + zv.y + zv.z + zv.w;
    float s2 = zv.x * zv.x + zv.y * zv.y + zv.z * zv.z + zv.w * zv.w;
    s = warp_sum(s);
    s2 = warp_sum(s2);
    float mu = s * (1.0f / 128.0f);
    float var = s2 * (1.0f / 128.0f) - mu * mu;
    float rs = rsqrtf(var + 1e-5f);
    float4 gv = *(const float4*)&g[lane << 2];
    float4 bv = *(const float4*)&b[lane << 2];
    float4 o;
    o.x = (zv.x - mu) * rs * gv.x + bv.x;
    o.y = (zv.y - mu) * rs * gv.y + bv.y;
    o.z = (zv.z - mu) * rs * gv.z + bv.z;
    o.w = (zv.w - mu) * rs * gv.w + bv.w;
    *(float4*)&g_zn[row * INDIM + (lane << 2)] = o;
}

// ---------------------------------------------------------------------------
// Tiled GEMM: C[M=65536, NTOT] = A[M,128] @ B[128,NTOT], 64x64 tiles,
// 256 threads, 4x4 microtile per thread.
// MODE 0: A=zn, scatter qkv into g_q/g_k/g_v     (NTOT=384)
// MODE 1: A=zn, sigmoid(x+bias) -> g_gate        (NTOT=128)
// MODE 2: A=gate*ao, x+bias -> dout              (NTOT=128)
// ---------------------------------------------------------------------------
template <int MODE>
__global__ void __launch_bounds__(256) gemm_kernel(
    int NTOT, const float* __restrict__ B,
    const float* __restrict__ bias, float* __restrict__ dout)
{
    __shared__ float As[64][68];   // [k][m], padded
    __shared__ float Bs[64][68];   // [k][n], padded

    int tid = threadIdx.x;
    int tx = tid & 15, ty = tid >> 4;
    int m0 = blockIdx.y << 6, n0 = blockIdx.x << 6;
    int lr = tid >> 4, lc = (tid & 15) << 2;

    float acc[4][4];
    #pragma unroll
    for (int i = 0; i < 4; i++)
        #pragma unroll
        for (int j = 0; j < 4; j++) acc[i][j] = 0.0f;

    for (int kc = 0; kc < 128; kc += 64) {
        #pragma unroll
        for (int rr = 0; rr < 4; rr++) {
            int row = lr + (rr << 4);
            int gi = (m0 + row) * INDIM + kc + lc;
            float4 a;
            if (MODE == 2) {
                float4 x = *(const float4*)&g_ao[gi];
                float4 gt = *(const float4*)&g_gate[gi];
                a.x = x.x * gt.x; a.y = x.y * gt.y;
                a.z = x.z * gt.z; a.w = x.w * gt.w;
            } else {
                a = *(const float4*)&g_zn[gi];
            }
            As[lc + 0][row] = a.x; As[lc + 1][row] = a.y;
            As[lc + 2][row] = a.z; As[lc + 3][row] = a.w;
            float4 b4 = *(const float4*)&B[(kc + row) * NTOT + n0 + lc];
            *(float4*)&Bs[row][lc] = b4;
        }
        __syncthreads();
        #pragma unroll 8
        for (int k = 0; k < 64; k++) {
            float4 av = *(const float4*)&As[k][ty << 2];
            float4 bv = *(const float4*)&Bs[k][tx << 2];
            float am[4] = {av.x, av.y, av.z, av.w};
            float bm[4] = {bv.x, bv.y, bv.z, bv.w};
            #pragma unroll
            for (int i = 0; i < 4; i++)
                #pragma unroll
                for (int j = 0; j < 4; j++)
                    acc[i][j] = fmaf(am[i], bm[j], acc[i][j]);
        }
        __syncthreads();
    }

    int nb = n0 + (tx << 2);
    #pragma unroll
    for (int mm = 0; mm < 4; mm++) {
        int p = m0 + (ty << 2) + mm;
        float4 res = make_float4(acc[mm][0], acc[mm][1], acc[mm][2], acc[mm][3]);
        if (MODE == 0) {
            // qkv scatter: seg(q/k/v), h, d; a 4-wide group never straddles h/seg
            int seg = nb >> 7, nl = nb & 127, h = nl >> 5, d = nl & 31;
            int r = p >> 8, i = p & 255;
            float* dst = (seg == 0) ? g_q : ((seg == 1) ? g_k : g_v);
            *(float4*)&dst[((r * NH + h) * NSEQ + i) * HD + d] = res;
        } else if (MODE == 1) {
            float4 bb = *(const float4*)&bias[nb];
            res.x = 1.0f / (1.0f + __expf(-(res.x + bb.x)));
            res.y = 1.0f / (1.0f + __expf(-(res.y + bb.y)));
            res.z = 1.0f / (1.0f + __expf(-(res.z + bb.z)));
            res.w = 1.0f / (1.0f + __expf(-(res.w + bb.w)));
            *(float4*)&g_gate[p * INDIM + nb] = res;
        } else {
            float4 bb = *(const float4*)&bias[nb];
            res.x += bb.x; res.y += bb.y; res.z += bb.z; res.w += bb.w;
            *(float4*)&dout[p * INDIM + nb] = res;
        }
    }
}

// ---------------------------------------------------------------------------
// Pair bias: pb[h][i][j] = zn[(i,j)] . w_pair[:,h].  One warp per position.
// ---------------------------------------------------------------------------
__global__ void __launch_bounds__(128) pb_kernel(const float* __restrict__ w_pair)
{
    int w = threadIdx.x >> 5, lane = threadIdx.x & 31;
    int p = blockIdx.x * 4 + w;
    float4 zv = *(const float4*)&g_zn[p * INDIM + (lane << 2)];
    const float4* W = (const float4*)w_pair;  // row k -> 4 heads
    int k0 = lane << 2;
    float4 w0 = W[k0], w1 = W[k0 + 1], w2 = W[k0 + 2], w3 = W[k0 + 3];
    float4 a;
    a.x = zv.x * w0.x + zv.y * w1.x + zv.z * w2.x + zv.w * w3.x;
    a.y = zv.x * w0.y + zv.y * w1.y + zv.z * w2.y + zv.w * w3.y;
    a.z = zv.x * w0.z + zv.y * w1.z + zv.z * w2.z + zv.w * w3.z;
    a.w = zv.x * w0.w + zv.y * w1.w + zv.z * w2.w + zv.w * w3.w;
    a.x = warp_sum(a.x); a.y = warp_sum(a.y);
    a.z = warp_sum(a.z); a.w = warp_sum(a.w);
    if (lane == 0) {
        g_pb[0 * NPOS + p] = a.x;
        g_pb[1 * NPOS + p] = a.y;
        g_pb[2 * NPOS + p] = a.z;
        g_pb[3 * NPOS + p] = a.w;
    }
}

// ---------------------------------------------------------------------------
// Attention: one block per (h, r). K,V in smem (stride-33 pad, conflict-free).
// Each warp: 32 i-rows, processed 4 at a time; j split 8-per-lane.
// Softmax faithful to ref: masked logits = -1e-9 (NOT -inf), max-subtracted.
// smem: Ks[256*33] | Vs[256*33] | Aw[8*4*256] | msk[256]  = 101376 B
// ---------------------------------------------------------------------------
__global__ void __launch_bounds__(256) attn_kernel(const int* __restrict__ smask)
{
    extern __shared__ float sm[];
    float* Ks = sm;                 // 8448 floats
    float* Vs = sm + 8448;          // 8448 floats
    float* Aw = sm + 16896;         // 8192 floats
    int*   msk = (int*)(sm + 25088);

    int h = blockIdx.x, r = blockIdx.y;
    int tid = threadIdx.x;
    int base = (r * NH + h) << 13;   // *(256*32)

    #pragma unroll
    for (int t = 0; t < 8; t++) {
        int idx = (tid << 2) + (t << 10);
        int j = idx >> 5, d = idx & 31;
        float4 k4 = *(const float4*)&g_k[base + idx];
        Ks[j * 33 + d] = k4.x; Ks[j * 33 + d + 1] = k4.y;
        Ks[j * 33 + d + 2] = k4.z; Ks[j * 33 + d + 3] = k4.w;
        float4 v4 = *(const float4*)&g_v[base + idx];
        Vs[j * 33 + d] = v4.x; Vs[j * 33 + d + 1] = v4.y;
        Vs[j * 33 + d + 2] = v4.z; Vs[j * 33 + d + 3] = v4.w;
    }
    if (tid < 256) msk[tid] = (smask[tid] == 0) ? 1 : 0;
    __syncthreads();

    int w = tid >> 5, lane = tid & 31;
    const float invs = 0.17677669529663687f;  // 1/sqrt(32)

    for (int gp = 0; gp < 8; gp++) {
        int i0 = (w << 5) + (gp << 2);
        float qreg[4];
        #pragma unroll
        for (int ii = 0; ii < 4; ii++)
            qreg[ii] = g_q[base + ((i0 + ii) << 5) + lane];

        float acc[4][8];
        #pragma unroll
        for (int ii = 0; ii < 4; ii++)
            #pragma unroll
            for (int jj = 0; jj < 8; jj++) acc[ii][jj] = 0.0f;

        #pragma unroll 4
        for (int d = 0; d < 32; d++) {
            float kv[8];
            #pragma unroll
            for (int jj = 0; jj < 8; jj++)
                kv[jj] = Ks[((jj << 5) + lane) * 33 + d];
            #pragma unroll
            for (int ii = 0; ii < 4; ii++) {
                float qv = __shfl_sync(0xffffffffu, qreg[ii], d);
                #pragma unroll
                for (int jj = 0; jj < 8; jj++)
                    acc[ii][jj] = fmaf(qv, kv[jj], acc[ii][jj]);
            }
        }

        #pragma unroll
        for (int ii = 0; ii < 4; ii++) {
            int i = i0 + ii;
            int mi = msk[i];
            const float* pbrow = &g_pb[(h << 16) + (i << 8)];
            float l[8];
            float mx = -1e30f;
            #pragma unroll
            for (int jj = 0; jj < 8; jj++) {
                int j = (jj << 5) + lane;
                float lv = fmaf(acc[ii][jj], invs, pbrow[j]);
                if (mi ^ msk[j]) lv = -1e-9f;   // faithful: -1e-9, not -inf
                l[jj] = lv;
                mx = fmaxf(mx, lv);
            }
            mx = warp_max(mx);
            float s = 0.0f;
            #pragma unroll
            for (int jj = 0; jj < 8; jj++) {
                float e = __expf(l[jj] - mx);
                l[jj] = e;
                s += e;
            }
            s = warp_sum(s);
            float inv = 1.0f / s;
            float* arow = &Aw[((w << 2) + ii) << 8];
            #pragma unroll
            for (int jj = 0; jj < 8; jj++)
                arow[(jj << 5) + lane] = l[jj] * inv;
        }
        __syncwarp();

        // O = A @ V  (lane = d)
        float o[4] = {0.0f, 0.0f, 0.0f, 0.0f};
        const float* aw0 = &Aw[(w << 2) << 8];
        #pragma unroll 4
        for (int j0 = 0; j0 < 256; j0 += 4) {
            float vv0 = Vs[(j0 + 0) * 33 + lane];
            float vv1 = Vs[(j0 + 1) * 33 + lane];
            float vv2 = Vs[(j0 + 2) * 33 + lane];
            float vv3 = Vs[(j0 + 3) * 33 + lane];
            #pragma unroll
            for (int ii = 0; ii < 4; ii++) {
                float4 a4 = *(const float4*)&aw0[(ii << 8) + j0];
                o[ii] = fmaf(a4.x, vv0, o[ii]);
                o[ii] = fmaf(a4.y, vv1, o[ii]);
                o[ii] = fmaf(a4.z, vv2, o[ii]);
                o[ii] = fmaf(a4.w, vv3, o[ii]);
            }
        }
        #pragma unroll
        for (int ii = 0; ii < 4; ii++)
            g_ao[((r << 8) + i0 + ii) * INDIM + (h << 5) + lane] = o[ii];
        __syncwarp();
    }
}

// ---------------------------------------------------------------------------
extern "C" void kernel_launch(void* const* d_in, const int* in_sizes, int n_in,
                              void* d_out, int out_size)
{
    const float* z      = (const float*)d_in[0];
    const int*   smask  = (const int*)  d_in[1];
    const float* ln_g   = (const float*)d_in[2];
    const float* ln_b   = (const float*)d_in[3];
    const float* w_qkv  = (const float*)d_in[4];
    const float* w_pair = (const float*)d_in[5];
    const float* w_gate = (const float*)d_in[6];
    const float* b_gate = (const float*)d_in[7];
    const float* w_out  = (const float*)d_in[8];
    const float* b_out  = (const float*)d_in[9];
    float* out = (float*)d_out;

    ln_kernel<<<8192, 256>>>(z, ln_g, ln_b);
    gemm_kernel<0><<<dim3(6, 1024), 256>>>(384, w_qkv, nullptr, nullptr);
    pb_kernel<<<16384, 128>>>(w_pair);
    gemm_kernel<1><<<dim3(2, 1024), 256>>>(128, w_gate, b_gate, nullptr);

    const int ATT_SMEM = 101376;
    cudaFuncSetAttribute(attn_kernel,
                         cudaFuncAttributeMaxDynamicSharedMemorySize, ATT_SMEM);
    attn_kernel<<<dim3(4, 256), 256, ATT_SMEM>>>(smask);

    gemm_kernel<2><<<dim3(2, 1024), 256>>>(128, w_out, b_out, out);
}

// round 2
// speedup vs baseline: 1.0182x; 1.0182x over previous
#include <cuda_runtime.h>
#include <math.h>

// ---------------------------------------------------------------------------
// TriangleAttention  (B=1, N=256, IN_DIM=128, H=4, D=32)
// R2: all hot inner loops converted to packed fma.rn.f32x2 (2x FMA/issue).
// ---------------------------------------------------------------------------

#define NPOS 65536
#define NSEQ 256
#define INDIM 128
#define NH 4
#define HD 32

typedef unsigned long long u64;

__device__ __forceinline__ u64 pk2(float lo, float hi) {
    u64 r; asm("mov.b64 %0, {%1,%2};" : "=l"(r) : "f"(lo), "f"(hi)); return r;
}
__device__ __forceinline__ u64 dup2(float v) { return pk2(v, v); }
__device__ __forceinline__ void upk2(u64 p, float& lo, float& hi) {
    asm("mov.b64 {%0,%1}, %2;" : "=f"(lo), "=f"(hi) : "l"(p));
}
__device__ __forceinline__ u64 ffma2(u64 a, u64 b, u64 c) {
    u64 d; asm("fma.rn.f32x2 %0, %1, %2, %3;" : "=l"(d) : "l"(a), "l"(b), "l"(c));
    return d;
}

// Scratch
__device__ float g_zn[NPOS * INDIM];
__device__ float g_q[NPOS * INDIM];      // [r][h][i][d]
__device__ float g_k[NPOS * INDIM];      // [r][h][j][d]
__device__ float g_v[NPOS * INDIM];      // [r][h][j][d]
__device__ float g_pb[NH * NPOS];        // [h][i][j]
__device__ float g_gate[NPOS * INDIM];
__device__ float g_ao[NPOS * INDIM];

__device__ __forceinline__ float warp_sum(float v) {
    #pragma unroll
    for (int o = 16; o; o >>= 1) v += __shfl_xor_sync(0xffffffffu, v, o);
    return v;
}
__device__ __forceinline__ float warp_max(float v) {
    #pragma unroll
    for (int o = 16; o; o >>= 1) v = fmaxf(v, __shfl_xor_sync(0xffffffffu, v, o));
    return v;
}

// ---------------------------------------------------------------------------
__global__ void __launch_bounds__(256) ln_kernel(
    const float* __restrict__ z, const float* __restrict__ g,
    const float* __restrict__ b)
{
    int w = threadIdx.x >> 5, lane = threadIdx.x & 31;
    int row = blockIdx.x * 8 + w;
    float4 zv = *(const float4*)&z[row * INDIM + (lane << 2)];
    float s  = zv.x + zv.y + zv.z + zv.w;
    float s2 = zv.x * zv.x + zv.y * zv.y + zv.z * zv.z + zv.w * zv.w;
    s = warp_sum(s);
    s2 = warp_sum(s2);
    float mu = s * (1.0f / 128.0f);
    float var = s2 * (1.0f / 128.0f) - mu * mu;
    float rs = rsqrtf(var + 1e-5f);
    float4 gv = *(const float4*)&g[lane << 2];
    float4 bv = *(const float4*)&b[lane << 2];
    float4 o;
    o.x = (zv.x - mu) * rs * gv.x + bv.x;
    o.y = (zv.y - mu) * rs * gv.y + bv.y;
    o.z = (zv.z - mu) * rs * gv.z + bv.z;
    o.w = (zv.w - mu) * rs * gv.w + bv.w;
    *(float4*)&g_zn[row * INDIM + (lane << 2)] = o;
}

// ---------------------------------------------------------------------------
// 64x64-tile GEMM, 256 thr, 4x4 microtile, j packed as f32x2 pairs.
// ---------------------------------------------------------------------------
template <int MODE>
__global__ void __launch_bounds__(256) gemm_kernel(
    int NTOT, const float* __restrict__ B,
    const float* __restrict__ bias, float* __restrict__ dout)
{
    __shared__ float As[64][68];
    __shared__ float Bs[64][68];

    int tid = threadIdx.x;
    int tx = tid & 15, ty = tid >> 4;
    int m0 = blockIdx.y << 6, n0 = blockIdx.x << 6;
    int lr = tid >> 4, lc = (tid & 15) << 2;

    u64 acc2[4][2];
    #pragma unroll
    for (int i = 0; i < 4; i++) { acc2[i][0] = 0ull; acc2[i][1] = 0ull; }

    for (int kc = 0; kc < 128; kc += 64) {
        #pragma unroll
        for (int rr = 0; rr < 4; rr++) {
            int row = lr + (rr << 4);
            int gi = (m0 + row) * INDIM + kc + lc;
            float4 a;
            if (MODE == 2) {
                float4 x = *(const float4*)&g_ao[gi];
                float4 gt = *(const float4*)&g_gate[gi];
                a.x = x.x * gt.x; a.y = x.y * gt.y;
                a.z = x.z * gt.z; a.w = x.w * gt.w;
            } else {
                a = *(const float4*)&g_zn[gi];
            }
            As[lc + 0][row] = a.x; As[lc + 1][row] = a.y;
            As[lc + 2][row] = a.z; As[lc + 3][row] = a.w;
            float4 b4 = *(const float4*)&B[(kc + row) * NTOT + n0 + lc];
            *(float4*)&Bs[row][lc] = b4;
        }
        __syncthreads();
        #pragma unroll 8
        for (int k = 0; k < 64; k++) {
            float4 av = *(const float4*)&As[k][ty << 2];
            float4 bv = *(const float4*)&Bs[k][tx << 2];
            u64 b0 = pk2(bv.x, bv.y), b1 = pk2(bv.z, bv.w);
            u64 a;
            a = dup2(av.x);
            acc2[0][0] = ffma2(a, b0, acc2[0][0]);
            acc2[0][1] = ffma2(a, b1, acc2[0][1]);
            a = dup2(av.y);
            acc2[1][0] = ffma2(a, b0, acc2[1][0]);
            acc2[1][1] = ffma2(a, b1, acc2[1][1]);
            a = dup2(av.z);
            acc2[2][0] = ffma2(a, b0, acc2[2][0]);
            acc2[2][1] = ffma2(a, b1, acc2[2][1]);
            a = dup2(av.w);
            acc2[3][0] = ffma2(a, b0, acc2[3][0]);
            acc2[3][1] = ffma2(a, b1, acc2[3][1]);
        }
        __syncthreads();
    }

    int nb = n0 + (tx << 2);
    #pragma unroll
    for (int mm = 0; mm < 4; mm++) {
        int p = m0 + (ty << 2) + mm;
        float4 res;
        upk2(acc2[mm][0], res.x, res.y);
        upk2(acc2[mm][1], res.z, res.w);
        if (MODE == 0) {
            int seg = nb >> 7, nl = nb & 127, h = nl >> 5, d = nl & 31;
            int r = p >> 8, i = p & 255;
            float* dst = (seg == 0) ? g_q : ((seg == 1) ? g_k : g_v);
            *(float4*)&dst[((r * NH + h) * NSEQ + i) * HD + d] = res;
        } else if (MODE == 1) {
            float4 bb = *(const float4*)&bias[nb];
            res.x = 1.0f / (1.0f + __expf(-(res.x + bb.x)));
            res.y = 1.0f / (1.0f + __expf(-(res.y + bb.y)));
            res.z = 1.0f / (1.0f + __expf(-(res.z + bb.z)));
            res.w = 1.0f / (1.0f + __expf(-(res.w + bb.w)));
            *(float4*)&g_gate[p * INDIM + nb] = res;
        } else {
            float4 bb = *(const float4*)&bias[nb];
            res.x += bb.x; res.y += bb.y; res.z += bb.z; res.w += bb.w;
            *(float4*)&dout[p * INDIM + nb] = res;
        }
    }
}

// ---------------------------------------------------------------------------
__global__ void __launch_bounds__(128) pb_kernel(const float* __restrict__ w_pair)
{
    int w = threadIdx.x >> 5, lane = threadIdx.x & 31;
    int p = blockIdx.x * 4 + w;
    float4 zv = *(const float4*)&g_zn[p * INDIM + (lane << 2)];
    const float4* W = (const float4*)w_pair;
    int k0 = lane << 2;
    float4 w0 = W[k0], w1 = W[k0 + 1], w2 = W[k0 + 2], w3 = W[k0 + 3];
    float4 a;
    a.x = zv.x * w0.x + zv.y * w1.x + zv.z * w2.x + zv.w * w3.x;
    a.y = zv.x * w0.y + zv.y * w1.y + zv.z * w2.y + zv.w * w3.y;
    a.z = zv.x * w0.z + zv.y * w1.z + zv.z * w2.z + zv.w * w3.z;
    a.w = zv.x * w0.w + zv.y * w1.w + zv.z * w2.w + zv.w * w3.w;
    a.x = warp_sum(a.x); a.y = warp_sum(a.y);
    a.z = warp_sum(a.z); a.w = warp_sum(a.w);
    if (lane == 0) {
        g_pb[0 * NPOS + p] = a.x;
        g_pb[1 * NPOS + p] = a.y;
        g_pb[2 * NPOS + p] = a.z;
        g_pb[3 * NPOS + p] = a.w;
    }
}

// ---------------------------------------------------------------------------
// Attention per (h, r). QK: jj packed f32x2. AV: Aw stored ii-major [j][4]
// so one broadcast LDS.128 yields natural register pairs for f32x2.
// smem: Ks[256*33] | Vs[256*33] | Aw[8 warps][256][4] | msk[256]
// ---------------------------------------------------------------------------
__global__ void __launch_bounds__(256) attn_kernel(const int* __restrict__ smask)
{
    extern __shared__ float sm[];
    float* Ks = sm;                 // 8448 floats
    float* Vs = sm + 8448;          // 8448 floats
    float* Aw = sm + 16896;         // 8192 floats: [warp][j][ii]
    int*   msk = (int*)(sm + 25088);

    int h = blockIdx.x, r = blockIdx.y;
    int tid = threadIdx.x;
    int base = (r * NH + h) << 13;

    #pragma unroll
    for (int t = 0; t < 8; t++) {
        int idx = (tid << 2) + (t << 10);
        int j = idx >> 5, d = idx & 31;
        float4 k4 = *(const float4*)&g_k[base + idx];
        Ks[j * 33 + d] = k4.x; Ks[j * 33 + d + 1] = k4.y;
        Ks[j * 33 + d + 2] = k4.z; Ks[j * 33 + d + 3] = k4.w;
        float4 v4 = *(const float4*)&g_v[base + idx];
        Vs[j * 33 + d] = v4.x; Vs[j * 33 + d + 1] = v4.y;
        Vs[j * 33 + d + 2] = v4.z; Vs[j * 33 + d + 3] = v4.w;
    }
    if (tid < 256) msk[tid] = (smask[tid] == 0) ? 1 : 0;
    __syncthreads();

    int w = tid >> 5, lane = tid & 31;
    const float invs = 0.17677669529663687f;  // 1/sqrt(32)
    float* awb = &Aw[w << 10];                 // warp's [256][4] region

    for (int gp = 0; gp < 8; gp++) {
        int i0 = (w << 5) + (gp << 2);
        float qreg[4];
        #pragma unroll
        for (int ii = 0; ii < 4; ii++)
            qreg[ii] = g_q[base + ((i0 + ii) << 5) + lane];

        u64 acc2[4][4];
        #pragma unroll
        for (int ii = 0; ii < 4; ii++)
            #pragma unroll
            for (int t = 0; t < 4; t++) acc2[ii][t] = 0ull;

        #pragma unroll 4
        for (int d = 0; d < 32; d++) {
            float kv[8];
            #pragma unroll
            for (int jj = 0; jj < 8; jj++)
                kv[jj] = Ks[((jj << 5) + lane) * 33 + d];
            u64 kp[4];
            #pragma unroll
            for (int t = 0; t < 4; t++) kp[t] = pk2(kv[2 * t], kv[2 * t + 1]);
            #pragma unroll
            for (int ii = 0; ii < 4; ii++) {
                u64 q2 = dup2(__shfl_sync(0xffffffffu, qreg[ii], d));
                #pragma unroll
                for (int t = 0; t < 4; t++)
                    acc2[ii][t] = ffma2(q2, kp[t], acc2[ii][t]);
            }
        }

        float prob[4][8];
        #pragma unroll
        for (int ii = 0; ii < 4; ii++) {
            int i = i0 + ii;
            int mi = msk[i];
            const float* pbrow = &g_pb[(h << 16) + (i << 8)];
            float l[8];
            #pragma unroll
            for (int t = 0; t < 4; t++)
                upk2(acc2[ii][t], l[2 * t], l[2 * t + 1]);
            float mx = -1e30f;
            #pragma unroll
            for (int jj = 0; jj < 8; jj++) {
                int j = (jj << 5) + lane;
                float lv = fmaf(l[jj], invs, pbrow[j]);
                if (mi ^ msk[j]) lv = -1e-9f;   // faithful: -1e-9, not -inf
                l[jj] = lv;
                mx = fmaxf(mx, lv);
            }
            mx = warp_max(mx);
            float s = 0.0f;
            #pragma unroll
            for (int jj = 0; jj < 8; jj++) {
                float e = __expf(l[jj] - mx);
                l[jj] = e;
                s += e;
            }
            s = warp_sum(s);
            float inv = 1.0f / s;
            #pragma unroll
            for (int jj = 0; jj < 8; jj++) prob[ii][jj] = l[jj] * inv;
        }
        // store probs ii-major: Aw[w][j][ii]
        #pragma unroll
        for (int jj = 0; jj < 8; jj++) {
            float4 a4 = make_float4(prob[0][jj], prob[1][jj],
                                    prob[2][jj], prob[3][jj]);
            *(float4*)&awb[(((jj << 5) + lane)) << 2] = a4;
        }
        __syncwarp();

        // O = A @ V  (lane = d); a4 = probs for 4 i-rows at j (broadcast)
        u64 o2[2] = {0ull, 0ull};
        #pragma unroll 8
        for (int j = 0; j < 256; j++) {
            u64 v2 = dup2(Vs[j * 33 + lane]);
            float4 a4 = *(const float4*)&awb[j << 2];
            o2[0] = ffma2(pk2(a4.x, a4.y), v2, o2[0]);
            o2[1] = ffma2(pk2(a4.z, a4.w), v2, o2[1]);
        }
        float o0, o1, o2f, o3;
        upk2(o2[0], o0, o1);
        upk2(o2[1], o2f, o3);
        int ob = ((r << 8) + i0) * INDIM + (h << 5) + lane;
        g_ao[ob] = o0;
        g_ao[ob + INDIM] = o1;
        g_ao[ob + 2 * INDIM] = o2f;
        g_ao[ob + 3 * INDIM] = o3;
        __syncwarp();
    }
}

// ---------------------------------------------------------------------------
extern "C" void kernel_launch(void* const* d_in, const int* in_sizes, int n_in,
                              void* d_out, int out_size)
{
    const float* z      = (const float*)d_in[0];
    const int*   smask  = (const int*)  d_in[1];
    const float* ln_g   = (const float*)d_in[2];
    const float* ln_b   = (const float*)d_in[3];
    const float* w_qkv  = (const float*)d_in[4];
    const float* w_pair = (const float*)d_in[5];
    const float* w_gate = (const float*)d_in[6];
    const float* b_gate = (const float*)d_in[7];
    const float* w_out  = (const float*)d_in[8];
    const float* b_out  = (const float*)d_in[9];
    float* out = (float*)d_out;

    ln_kernel<<<8192, 256>>>(z, ln_g, ln_b);
    gemm_kernel<0><<<dim3(6, 1024), 256>>>(384, w_qkv, nullptr, nullptr);
    pb_kernel<<<16384, 128>>>(w_pair);
    gemm_kernel<1><<<dim3(2, 1024), 256>>>(128, w_gate, b_gate, nullptr);

    const int ATT_SMEM = 101376;
    cudaFuncSetAttribute(attn_kernel,
                         cudaFuncAttributeMaxDynamicSharedMemorySize, ATT_SMEM);
    attn_kernel<<<dim3(4, 256), 256, ATT_SMEM>>>(smask);

    gemm_kernel<2><<<dim3(2, 1024), 256>>>(128, w_out, b_out, out);
}